// round 3
// baseline (speedup 1.0000x reference)
#include <cuda_runtime.h>
#include <math.h>

// Problem constants (B=1, C_IN=3, H=W=96, FEAT=64, GDIM=8, BLOCK=16)
#define Hh   96
#define Ww   96
#define HW   (96 * 96)
#define GD   8
#define FEAT 64
#define CIN  3
#define TWt  6   // (96+15)/16
#define THt  6

struct __align__(16) GParam {
    float cx, cy, ca, cb, cc;
    float r0, r1, r2;
    int tminx, tmaxx, tminy, tmaxy;
};

__device__ GParam g_gauss[HW];   // 442 KB scratch (device global: no allocations)

// ---------------------------------------------------------------------------
// Kernel 1: per-gaussian parameter computation.
// Each block first builds the collapsed conv+head weights in shared memory,
// then each thread handles one gaussian (= one pixel of the feature grid).
// ---------------------------------------------------------------------------
__global__ __launch_bounds__(256)
void gauss_params_kernel(const float* __restrict__ inp,
                         const float* __restrict__ w_enc,
                         const float* __restrict__ b_enc,
                         const float* __restrict__ w_head,
                         const float* __restrict__ b_head)
{
    __shared__ float sw[GD * 27];   // w_eff[o][ci*9+ky*3+kx]
    __shared__ float sb[GD];        // b_eff[o]

    const int tid = threadIdx.x;

    if (tid < GD * 27) {
        const int o = tid / 27, t = tid % 27;
        float acc = 0.f;
        #pragma unroll 8
        for (int c = 0; c < FEAT; ++c)
            acc += __ldg(&w_head[o * FEAT + c]) * __ldg(&w_enc[c * 27 + t]);
        sw[tid] = acc;
    } else if (tid < GD * 27 + GD) {
        const int o = tid - GD * 27;
        float acc = __ldg(&b_head[o]);
        #pragma unroll 8
        for (int c = 0; c < FEAT; ++c)
            acc += __ldg(&w_head[o * FEAT + c]) * __ldg(&b_enc[c]);
        sb[o] = acc;
    }
    __syncthreads();

    const int p = blockIdx.x * blockDim.x + tid;
    if (p >= HW) return;
    const int w = p % Ww;
    const int h = p / Ww;

    float pred[GD];
    #pragma unroll
    for (int o = 0; o < GD; ++o) pred[o] = sb[o];

    // Effective 3x3x3 conv, SAME zero padding (cross-correlation, no flip).
    #pragma unroll
    for (int ci = 0; ci < CIN; ++ci) {
        #pragma unroll
        for (int ky = 0; ky < 3; ++ky) {
            const int y = h + ky - 1;
            #pragma unroll
            for (int kx = 0; kx < 3; ++kx) {
                const int x = w + kx - 1;
                float v = 0.f;
                if (y >= 0 && y < Hh && x >= 0 && x < Ww)
                    v = __ldg(&inp[ci * HW + y * Ww + x]);
                const int t = ci * 9 + ky * 3 + kx;
                #pragma unroll
                for (int o = 0; o < GD; ++o)
                    pred[o] += v * sw[o * 27 + t];
            }
        }
    }

    // Activations (mirror reference formulas and ordering)
    const float theta = (1.f / (1.f + expf(-pred[3]))) * 6.283185307179586f;
    const float s0 = (1.f / (1.f + expf(-pred[4]))) * 0.5f + 1e-6f;
    const float s1 = (1.f / (1.f + expf(-pred[5]))) * 0.5f + 1e-6f;
    const float off0 = tanhf(pred[6]);
    const float off1 = tanhf(pred[7]);

    const float c = cosf(theta), s = sinf(theta);
    const float v0 = s0 * s0, v1 = s1 * s1;
    const float S00 = c * c * v0 + s * s * v1;
    const float S01 = c * s * (v0 - v1);
    const float S11 = s * s * v0 + c * c * v1;
    const float det = S00 * S11 - S01 * S01;
    const float inv_det = 1.f / det;
    const float ca =  S11 * inv_det;
    const float cb = -S01 * inv_det;
    const float cc =  S00 * inv_det;
    const float bmid = 0.5f * (S00 + S11);
    const float lam1 = bmid + sqrtf(fmaxf(0.1f, bmid * bmid - det));
    const float radius = ceilf(3.0f * sqrtf(lam1));

    // NDC -> pixel center (coord0 varies with w via yg, coord1 with h via xg)
    const float coord0 = 2.0f * (float)w / (float)Ww - 1.0f;
    const float coord1 = 2.0f * (float)h / (float)Hh - 1.0f;
    const float x_ndc = coord0 + 2.0f * off0 / (float)Ww - 1.0f / (float)Ww;
    const float y_ndc = coord1 + 2.0f * off1 / (float)Hh - 1.0f / (float)Hh;
    const float cx = 0.5f * (float)Ww * (x_ndc + 1.0f) - 0.5f;
    const float cy = 0.5f * (float)Hh * (y_ndc + 1.0f) - 0.5f;

    // Tile bounds: truncating int cast, then clip to [0, TW] — exact reference semantics.
    int tmin_x = min(max((int)((cx - radius) / 16.0f), 0), TWt);
    int tmax_x = min(max((int)((cx + radius) / 16.0f) + 1, 0), TWt);
    int tmin_y = min(max((int)((cy - radius) / 16.0f), 0), THt);
    int tmax_y = min(max((int)((cy + radius) / 16.0f) + 1, 0), THt);
    if (!(radius > 0.0f)) { tmax_x = tmin_x; tmax_y = tmin_y; }  // radius>0 gate (always true here, kept exact)

    GParam g;
    g.cx = cx; g.cy = cy; g.ca = ca; g.cb = cb; g.cc = cc;
    g.r0 = pred[0]; g.r1 = pred[1]; g.r2 = pred[2];
    g.tminx = tmin_x; g.tmaxx = tmax_x; g.tminy = tmin_y; g.tmaxy = tmax_y;
    g_gauss[p] = g;
}

// ---------------------------------------------------------------------------
// Kernel 2: per-pixel gather over the provably-sufficient 7x7 gaussian window.
// alpha >= 1/255 requires |d| <= 1.665 px (lam_max(Sigma) <= 0.25), and the
// center offset is tanh in (-1,1), so gaussians outside [p-2, p+4] in each
// axis can never pass the reference's valid mask. Tile checks only prune.
// Iteration order (gh asc, gw asc) matches the reference's sum-over-n order.
// ---------------------------------------------------------------------------
__global__ __launch_bounds__(256)
void raster_kernel(float* __restrict__ out)
{
    const int p = blockIdx.x * blockDim.x + threadIdx.x;
    if (p >= HW) return;
    const int px = p % Ww;
    const int py = p / Ww;
    const int tx = px >> 4;
    const int ty = py >> 4;
    const float fpx = (float)px;
    const float fpy = (float)py;

    float a0 = 0.f, a1 = 0.f, a2 = 0.f;

    const int h0 = max(py - 2, 0), h1 = min(py + 4, Hh - 1);
    const int w0 = max(px - 2, 0), w1 = min(px + 4, Ww - 1);

    for (int gh = h0; gh <= h1; ++gh) {
        const GParam* __restrict__ row = &g_gauss[gh * Ww];
        for (int gw = w0; gw <= w1; ++gw) {
            const GParam g = row[gw];
            const float dx = g.cx - fpx;
            const float dy = g.cy - fpy;
            const float sigma = 0.5f * (g.ca * dx * dx + g.cc * dy * dy) + g.cb * dx * dy;
            if (sigma < 0.f) continue;
            const float alpha = fminf(0.999f, expf(-sigma));
            if (alpha < (1.0f / 255.0f)) continue;
            if (tx < g.tminx || tx >= g.tmaxx || ty < g.tminy || ty >= g.tmaxy) continue;
            a0 += alpha * g.r0;
            a1 += alpha * g.r1;
            a2 += alpha * g.r2;
        }
    }

    out[0 * HW + p] = fminf(fmaxf(a0, 0.f), 1.f);
    out[1 * HW + p] = fminf(fmaxf(a1, 0.f), 1.f);
    out[2 * HW + p] = fminf(fmaxf(a2, 0.f), 1.f);
}

// ---------------------------------------------------------------------------
extern "C" void kernel_launch(void* const* d_in, const int* in_sizes, int n_in,
                              void* d_out, int out_size)
{
    const float* inp    = (const float*)d_in[0];
    const float* w_enc  = (const float*)d_in[1];
    const float* b_enc  = (const float*)d_in[2];
    const float* w_head = (const float*)d_in[3];
    const float* b_head = (const float*)d_in[4];
    float* out = (float*)d_out;

    const int blocks = (HW + 255) / 256;  // 36
    gauss_params_kernel<<<blocks, 256>>>(inp, w_enc, b_enc, w_head, b_head);
    raster_kernel<<<blocks, 256>>>(out);
}